// round 12
// baseline (speedup 1.0000x reference)
#include <cuda_runtime.h>
#include <cuda_fp16.h>
#include <cstdint>

#define TT 512
#define HF 256
#define VV 32
#define RD 4
#define F_LOG2E 1.4426950408889634f
#define F_LN2   0.6931471805599453f

__device__ __forceinline__ float ex2f_(float x){ float y; asm("ex2.approx.ftz.f32 %0, %1;" : "=f"(y) : "f"(x)); return y; }
__device__ __forceinline__ float lg2f_(float x){ float y; asm("lg2.approx.ftz.f32 %0, %1;" : "=f"(y) : "f"(x)); return y; }
__device__ __forceinline__ void cpa16(uint32_t s, const void* g){
  asm volatile("cp.async.cg.shared.global [%0], [%1], 16;" :: "r"(s), "l"(g));
}
#define CPCOMMIT() asm volatile("cp.async.commit_group;")
#define CPWAIT3()  asm volatile("cp.async.wait_group 3;")

__device__ __forceinline__ uint32_t h2u_(__half2 h){ uint32_t r; memcpy(&r, &h, 4); return r; }
__device__ __forceinline__ __half2 u2h_(uint32_t u){ __half2 r; memcpy(&r, &u, 4); return r; }

__device__ __forceinline__ int tgt_is64(const int* t32){
  int is64 = 1;
  #pragma unroll
  for (int k = 1; k < 64; k += 2) if (t32[k] != 0) is64 = 0;
  return is64;
}
__device__ __forceinline__ int ld_tgt(const void* traw, int is64, long long idx){
  return is64 ? (int)((const long long*)traw)[idx] : ((const int*)traw)[idx];
}

__global__ __launch_bounds__(64, 1)
void crf_kernel(const float* __restrict__ scores,
                const void*  __restrict__ traw,
                const float* __restrict__ w_tx,
                const float* __restrict__ w_init,
                const float* __restrict__ w_final,
                const float* __restrict__ w_dur,
                float* __restrict__ out)
{
  __shared__ __align__(16) float ring[2][RD*1024];   // per-warp cp.async ring
  __shared__ float exch[2][VV];
  __shared__ float numsm[64];
  __shared__ int   Ash[2];

  const int b    = blockIdx.x;
  const int tid  = threadIdx.x;
  const int lane = tid & 31;
  const int wid  = tid >> 5;           // 0 = forward, 1 = backward
  const float* sb = scores + (size_t)b * TT * 1024;
  const uint32_t rbase = (uint32_t)__cvta_generic_to_shared(&ring[wid][0]);
  const char*    rptr  = (const char*)&ring[wid][0];

  // cp.async dest offsets, 16B-XOR swizzle (chunk g=i*32+lane -> row=g>>3, c4=g&7 at c4^(row&7))
  uint32_t dsto[8];
  #pragma unroll
  for (int i = 0; i < 8; ++i){
    int g = i*32 + lane, row = g >> 3, c4 = g & 7;
    dsto[i] = (uint32_t)(row*128 + ((c4 ^ (row & 7)) * 16));
  }

  float c2[VV], u;
  if (wid == 0){
    #pragma unroll
    for (int i = 0; i < VV; ++i) c2[i] = (w_tx[i*VV + lane] + w_dur[i*VV + lane]) * F_LOG2E;
    u = ex2f_(w_init[lane] * F_LOG2E);
  } else {
    #pragma unroll
    for (int i = 0; i < VV; ++i) c2[i] = (w_tx[lane*VV + i] + w_dur[lane*VV + i]) * F_LOG2E;
    u = ex2f_(w_final[lane] * F_LOG2E);
  }

  // prologue: tiles 0..RD-2
  #pragma unroll
  for (int p = 0; p < RD-1; ++p){
    const char* g = (const char*)(wid == 0 ? sb + (size_t)p*1024
                                           : sb + (size_t)(TT-1-p)*1024);
    #pragma unroll
    for (int i = 0; i < 8; ++i) cpa16(rbase + (uint32_t)p*4096u + dsto[i], g + i*512 + lane*16);
    CPCOMMIT();
  }

  int A = 0;
  const __half2 hz = __float2half2_rn(0.f);

  if (wid == 0){
    // ---------------- FORWARD: u_{t+1}[j] = sum_i e_t[i][j] * u_t[i]
    uint32_t off8[8];
    #pragma unroll
    for (int k = 0; k < 8; ++k) off8[k] = (uint32_t)((((lane>>2) ^ k) * 16) + (lane & 3) * 4);

    for (int tb = 0; tb < HF; tb += 4){
      #pragma unroll
      for (int q = 0; q < 4; ++q){
        const int t = tb + q;
        { const int tl = t + RD - 1;
          if (tl < HF){
            const char* g = (const char*)(sb + (size_t)tl*1024);
            const uint32_t d = rbase + (uint32_t)(tl & (RD-1)) * 4096u;
            #pragma unroll
            for (int i = 0; i < 8; ++i) cpa16(d + dsto[i], g + i*512 + lane*16);
          }
          CPCOMMIT();
        }
        CPWAIT3();
        __syncwarp();

        // renorm every step to u[0] ~ 2^-2 (exact pow2), then pack u-pairs to f16x2
        float u0b = __shfl_sync(0xffffffffu, u, 0);
        int esh = ((__float_as_int(u0b) >> 23) & 255) - 125;   // exp-127+2
        esh = esh < -100 ? -100 : (esh > 100 ? 100 : esh);
        u *= __int_as_float((127 - esh) << 23);
        A += esh;
        float up = __shfl_xor_sync(0xffffffffu, u, 1);
        __half2 mp = (lane & 1) ? __floats2half2_rn(up, u) : __floats2half2_rn(u, up);
        uint32_t mpb = h2u_(mp);

        // e in f16x2 (u-independent)
        const char* tp = rptr + (t & (RD-1))*4096;
        __half2 e2[16];
        #pragma unroll
        for (int k = 0; k < 16; ++k){
          float s0 = *(const float*)(tp + (2*k  )*128 + off8[(2*k  ) & 7]);
          float s1 = *(const float*)(tp + (2*k+1)*128 + off8[(2*k+1) & 7]);
          float x0 = fmaf(s0, F_LOG2E, c2[2*k  ]);
          float x1 = fmaf(s1, F_LOG2E, c2[2*k+1]);
          e2[k] = h2exp2(__floats2half2_rn(x0, x1));
        }

        // dot with packed u-pair broadcasts
        __half2 a0 = hz, a1 = hz, a2 = hz, a3 = hz;
        #pragma unroll
        for (int k = 0; k < 16; k += 4){
          __half2 u0 = u2h_(__shfl_sync(0xffffffffu, mpb, 2*k    ));
          __half2 u1 = u2h_(__shfl_sync(0xffffffffu, mpb, 2*k + 2));
          __half2 u2 = u2h_(__shfl_sync(0xffffffffu, mpb, 2*k + 4));
          __half2 u3 = u2h_(__shfl_sync(0xffffffffu, mpb, 2*k + 6));
          a0 = __hfma2(e2[k  ], u0, a0);
          a1 = __hfma2(e2[k+1], u1, a1);
          a2 = __hfma2(e2[k+2], u2, a2);
          a3 = __hfma2(e2[k+3], u3, a3);
        }
        float2 f0 = __half22float2(__hadd2(a0, a1));
        float2 f1 = __half22float2(__hadd2(a2, a3));
        u = (f0.x + f0.y) + (f1.x + f1.y);
      }
    }
  } else {
    // ---------------- BACKWARD: u_t[i] = sum_j e_t[i][j] * u_{t+1}[j], tiles 511..256
    uint32_t roff[8];
    #pragma unroll
    for (int k = 0; k < 8; ++k) roff[k] = (uint32_t)((k ^ (lane & 7)) * 16);
    const uint32_t lrow = (uint32_t)(lane*128);

    for (int tb = 0; tb < HF; tb += 4){
      #pragma unroll
      for (int q = 0; q < 4; ++q){
        const int t = tb + q;
        { const int tl = t + RD - 1;
          if (tl < HF){
            const char* g = (const char*)(sb + (size_t)(TT-1-tl)*1024);
            const uint32_t d = rbase + (uint32_t)(tl & (RD-1)) * 4096u;
            #pragma unroll
            for (int i = 0; i < 8; ++i) cpa16(d + dsto[i], g + i*512 + lane*16);
          }
          CPCOMMIT();
        }
        CPWAIT3();
        __syncwarp();

        float u0b = __shfl_sync(0xffffffffu, u, 0);
        int esh = ((__float_as_int(u0b) >> 23) & 255) - 125;
        esh = esh < -100 ? -100 : (esh > 100 ? 100 : esh);
        u *= __int_as_float((127 - esh) << 23);
        A += esh;
        float up = __shfl_xor_sync(0xffffffffu, u, 1);
        __half2 mp = (lane & 1) ? __floats2half2_rn(up, u) : __floats2half2_rn(u, up);
        uint32_t mpb = h2u_(mp);

        const char* tp = rptr + (t & (RD-1))*4096 + lrow;
        __half2 e2[16];
        #pragma unroll
        for (int c4 = 0; c4 < 8; ++c4){
          float4 v = *(const float4*)(tp + roff[c4]);
          float x0 = fmaf(v.x, F_LOG2E, c2[4*c4  ]);
          float x1 = fmaf(v.y, F_LOG2E, c2[4*c4+1]);
          float x2 = fmaf(v.z, F_LOG2E, c2[4*c4+2]);
          float x3 = fmaf(v.w, F_LOG2E, c2[4*c4+3]);
          e2[2*c4  ] = h2exp2(__floats2half2_rn(x0, x1));
          e2[2*c4+1] = h2exp2(__floats2half2_rn(x2, x3));
        }

        __half2 a0 = hz, a1 = hz, a2 = hz, a3 = hz;
        #pragma unroll
        for (int k = 0; k < 16; k += 4){
          __half2 u0 = u2h_(__shfl_sync(0xffffffffu, mpb, 2*k    ));
          __half2 u1 = u2h_(__shfl_sync(0xffffffffu, mpb, 2*k + 2));
          __half2 u2 = u2h_(__shfl_sync(0xffffffffu, mpb, 2*k + 4));
          __half2 u3 = u2h_(__shfl_sync(0xffffffffu, mpb, 2*k + 6));
          a0 = __hfma2(e2[k  ], u0, a0);
          a1 = __hfma2(e2[k+1], u1, a1);
          a2 = __hfma2(e2[k+2], u2, a2);
          a3 = __hfma2(e2[k+3], u3, a3);
        }
        float2 f0 = __half22float2(__hadd2(a0, a1));
        float2 f1 = __half22float2(__hadd2(a2, a3));
        u = (f0.x + f0.y) + (f1.x + f1.y);
      }
    }
  }

  exch[wid][lane] = u;
  if (lane == 0) Ash[wid] = A;

  // ---------------- numerator (exact f32): thread tid gathers steps [tid*8, tid*8+8)
  const int is64 = tgt_is64((const int*)traw);
  const long long tbase = (long long)b * (TT+1);
  float np = 0.f;
  int tga = ld_tgt(traw, is64, tbase + tid*8);
  #pragma unroll
  for (int k = 0; k < 8; ++k){
    int tgb = ld_tgt(traw, is64, tbase + tid*8 + k + 1);
    int ix = tga*VV + tgb;
    np += sb[(size_t)(tid*8 + k)*1024 + ix] + w_tx[ix] + w_dur[ix];
    tga = tgb;
  }
  numsm[tid] = np;
  __syncthreads();

  if (wid == 0){
    float term = exch[0][lane] * exch[1][lane];   // Z = sum_j alpha[j]*beta[j]
    float ns   = numsm[lane] + numsm[32 + lane];
    #pragma unroll
    for (int o = 16; o; o >>= 1){
      term += __shfl_xor_sync(0xffffffffu, term, o);
      ns   += __shfl_xor_sync(0xffffffffu, ns,   o);
    }
    if (lane == 0){
      int t0 = ld_tgt(traw, is64, tbase);
      int tT = ld_tgt(traw, is64, tbase + TT);
      float num = ns + w_init[t0] + w_final[tT];
      out[b] = num - F_LN2 * (lg2f_(term) + (float)(Ash[0] + Ash[1]));
    }
  }
}

extern "C" void kernel_launch(void* const* d_in, const int* in_sizes, int n_in,
                              void* d_out, int out_size)
{
  const float* scores  = (const float*)d_in[0];
  const void*  targets = d_in[1];
  const float* w_tx    = (const float*)d_in[2];
  const float* w_init  = (const float*)d_in[3];
  const float* w_final = (const float*)d_in[4];
  const float* w_dur   = (const float*)d_in[5];
  float* out = (float*)d_out;

  crf_kernel<<<64, 64>>>(scores, targets, w_tx, w_init, w_final, w_dur, out);
}

// round 13
// speedup vs baseline: 1.3257x; 1.3257x over previous
#include <cuda_runtime.h>
#include <cstdint>

#define TT   512
#define VV   32
#define LSC  208          // scan length each direction (multiple of 4)
#define MID  96           // middle chunk steps (512 - 2*208)
#define RD   4            // scan ring depth
#define NSTG 4            // chunk ring depth
#define F_LOG2E 1.4426950408889634f
#define F_LN2   0.6931471805599453f

typedef unsigned long long ull;

__device__ float g_P[64*VV*VV];
__device__ float g_Ac[64];
__device__ int   g_flag[64];     // zero-init; consumer resets after use (replay-safe)

__device__ __forceinline__ float ex2f_(float x){ float y; asm("ex2.approx.ftz.f32 %0, %1;" : "=f"(y) : "f"(x)); return y; }
__device__ __forceinline__ float lg2f_(float x){ float y; asm("lg2.approx.ftz.f32 %0, %1;" : "=f"(y) : "f"(x)); return y; }
__device__ __forceinline__ ull fma2_(ull a, ull b, ull c){ ull r; asm("fma.rn.f32x2 %0, %1, %2, %3;" : "=l"(r) : "l"(a), "l"(b), "l"(c)); return r; }
__device__ __forceinline__ ull pack2_(float lo, float hi){ ull r; asm("mov.b64 %0, {%1, %2};" : "=l"(r) : "f"(lo), "f"(hi)); return r; }
__device__ __forceinline__ void unpack2_(ull v, float& lo, float& hi){ asm("mov.b64 {%0, %1}, %2;" : "=f"(lo), "=f"(hi) : "l"(v)); }
__device__ __forceinline__ void cpa16(uint32_t s, const void* g){
  asm volatile("cp.async.cg.shared.global [%0], [%1], 16;" :: "r"(s), "l"(g));
}
#define CPCOMMIT() asm volatile("cp.async.commit_group;")
#define CPWAIT3()  asm volatile("cp.async.wait_group 3;")
#define CPWAIT2()  asm volatile("cp.async.wait_group 2;")

__device__ __forceinline__ void st_release_(int* p, int v){
  asm volatile("st.release.gpu.global.s32 [%0], %1;" :: "l"(p), "r"(v) : "memory");
}
__device__ __forceinline__ int ld_acquire_(const int* p){
  int v; asm volatile("ld.acquire.gpu.global.s32 %0, [%1];" : "=r"(v) : "l"(p) : "memory");
  return v;
}

__device__ __forceinline__ int tgt_is64(const int* t32){
  int is64 = 1;
  #pragma unroll
  for (int k = 1; k < 64; k += 2) if (t32[k] != 0) is64 = 0;
  return is64;
}
__device__ __forceinline__ int ld_tgt(const void* traw, int is64, long long idx){
  return is64 ? (int)((const long long*)traw)[idx] : ((const int*)traw)[idx];
}

__global__ __launch_bounds__(128, 1)
void crf_main(const float* __restrict__ scores,
              const void*  __restrict__ traw,
              const float* __restrict__ w_tx,
              const float* __restrict__ w_init,
              const float* __restrict__ w_final,
              const float* __restrict__ w_dur,
              float* __restrict__ out)
{
  __shared__ __align__(16) char pool[33600];
  const int bid  = blockIdx.x;
  const int tid  = threadIdx.x;
  const int lane = tid & 31;
  const int wid  = tid >> 5;

  if (bid < 64){
    // ================= SCAN CTA: fwd t in [0,LSC), bwd t in [TT-LSC, TT) ==============
    const int b = bid;
    float (*ring)[RD*1024] = (float(*)[RD*1024])(pool);      // 2 x 16KB
    float (*exch)[VV]      = (float(*)[VV])(pool + 32768);   // 2 x 32
    float* numsm           = (float*)(pool + 33024);         // 128
    int*   Ash             = (int*)  (pool + 33536);         // 2
    const float* sb = scores + (size_t)b * TT * 1024;

    if (wid < 2){
      const uint32_t rbase = (uint32_t)__cvta_generic_to_shared(&ring[wid][0]);
      const char*    rptr  = (const char*)&ring[wid][0];

      uint32_t dsto[8];
      #pragma unroll
      for (int i = 0; i < 8; ++i){
        int g = i*32 + lane, row = g >> 3, c4 = g & 7;
        dsto[i] = (uint32_t)(row*128 + ((c4 ^ (row & 7)) * 16));
      }

      float c2[VV], u;
      if (wid == 0){
        #pragma unroll
        for (int i = 0; i < VV; ++i) c2[i] = (w_tx[i*VV + lane] + w_dur[i*VV + lane]) * F_LOG2E;
        u = ex2f_(w_init[lane] * F_LOG2E);
      } else {
        #pragma unroll
        for (int i = 0; i < VV; ++i) c2[i] = (w_tx[lane*VV + i] + w_dur[lane*VV + i]) * F_LOG2E;
        u = ex2f_(w_final[lane] * F_LOG2E);
      }

      int A = 0;

      if (wid == 0){
        // FORWARD
        #pragma unroll
        for (int p = 0; p < RD-1; ++p){
          const char* g = (const char*)(sb + (size_t)p*1024);
          #pragma unroll
          for (int i = 0; i < 8; ++i) cpa16(rbase + (uint32_t)p*4096u + dsto[i], g + i*512 + lane*16);
          CPCOMMIT();
        }
        uint32_t off8[8];
        #pragma unroll
        for (int k = 0; k < 8; ++k) off8[k] = (uint32_t)((((lane>>2) ^ k) * 16) + (lane & 3) * 4);

        for (int tb = 0; tb < LSC; tb += 4){
          #pragma unroll
          for (int q = 0; q < 4; ++q){
            const int t = tb + q;
            { const int tl = t + RD - 1;
              if (tl < LSC){
                const char* g = (const char*)(sb + (size_t)tl*1024);
                const uint32_t d = rbase + (uint32_t)(tl & (RD-1)) * 4096u;
                #pragma unroll
                for (int i = 0; i < 8; ++i) cpa16(d + dsto[i], g + i*512 + lane*16);
              }
              CPCOMMIT();
            }
            CPWAIT3();
            __syncwarp();
            const char* tp = rptr + (t & (RD-1))*4096;
            float a0=0.f, a1=0.f, a2=0.f, a3=0.f;
            #pragma unroll
            for (int i = 0; i < VV; i += 4){
              float s0 = *(const float*)(tp + (i  )*128 + off8[(i  ) & 7]);
              float s1 = *(const float*)(tp + (i+1)*128 + off8[(i+1) & 7]);
              float s2 = *(const float*)(tp + (i+2)*128 + off8[(i+2) & 7]);
              float s3 = *(const float*)(tp + (i+3)*128 + off8[(i+3) & 7]);
              float u0 = __shfl_sync(0xffffffffu, u, i  );
              float u1 = __shfl_sync(0xffffffffu, u, i+1);
              float u2 = __shfl_sync(0xffffffffu, u, i+2);
              float u3 = __shfl_sync(0xffffffffu, u, i+3);
              a0 = fmaf(ex2f_(fmaf(s0, F_LOG2E, c2[i  ])), u0, a0);
              a1 = fmaf(ex2f_(fmaf(s1, F_LOG2E, c2[i+1])), u1, a1);
              a2 = fmaf(ex2f_(fmaf(s2, F_LOG2E, c2[i+2])), u2, a2);
              a3 = fmaf(ex2f_(fmaf(s3, F_LOG2E, c2[i+3])), u3, a3);
            }
            u = (a0 + a1) + (a2 + a3);
          }
          float m = u;
          #pragma unroll
          for (int o = 16; o; o >>= 1) m = fmaxf(m, __shfl_xor_sync(0xffffffffu, m, o));
          int esh = ((__float_as_int(m) >> 23) & 255) - 127;
          esh = esh < -126 ? -126 : (esh > 126 ? 126 : esh);
          u *= __int_as_float((127 - esh) << 23);
          A += esh;
        }
      } else {
        // BACKWARD
        #pragma unroll
        for (int p = 0; p < RD-1; ++p){
          const char* g = (const char*)(sb + (size_t)(TT-1-p)*1024);
          #pragma unroll
          for (int i = 0; i < 8; ++i) cpa16(rbase + (uint32_t)p*4096u + dsto[i], g + i*512 + lane*16);
          CPCOMMIT();
        }
        uint32_t roff[8];
        #pragma unroll
        for (int k = 0; k < 8; ++k) roff[k] = (uint32_t)((k ^ (lane & 7)) * 16);
        const uint32_t lrow = (uint32_t)(lane*128);

        for (int tb = 0; tb < LSC; tb += 4){
          #pragma unroll
          for (int q = 0; q < 4; ++q){
            const int t = tb + q;
            { const int tl = t + RD - 1;
              if (tl < LSC){
                const char* g = (const char*)(sb + (size_t)(TT-1-tl)*1024);
                const uint32_t d = rbase + (uint32_t)(tl & (RD-1)) * 4096u;
                #pragma unroll
                for (int i = 0; i < 8; ++i) cpa16(d + dsto[i], g + i*512 + lane*16);
              }
              CPCOMMIT();
            }
            CPWAIT3();
            __syncwarp();
            const char* tp = rptr + (t & (RD-1))*4096 + lrow;
            float a0=0.f, a1=0.f, a2=0.f, a3=0.f;
            #pragma unroll
            for (int c4 = 0; c4 < 8; ++c4){
              float4 v = *(const float4*)(tp + roff[c4]);
              const int jj = c4*4;
              float u0 = __shfl_sync(0xffffffffu, u, jj  );
              float u1 = __shfl_sync(0xffffffffu, u, jj+1);
              float u2 = __shfl_sync(0xffffffffu, u, jj+2);
              float u3 = __shfl_sync(0xffffffffu, u, jj+3);
              a0 = fmaf(ex2f_(fmaf(v.x, F_LOG2E, c2[jj  ])), u0, a0);
              a1 = fmaf(ex2f_(fmaf(v.y, F_LOG2E, c2[jj+1])), u1, a1);
              a2 = fmaf(ex2f_(fmaf(v.z, F_LOG2E, c2[jj+2])), u2, a2);
              a3 = fmaf(ex2f_(fmaf(v.w, F_LOG2E, c2[jj+3])), u3, a3);
            }
            u = (a0 + a1) + (a2 + a3);
          }
          float m = u;
          #pragma unroll
          for (int o = 16; o; o >>= 1) m = fmaxf(m, __shfl_xor_sync(0xffffffffu, m, o));
          int esh = ((__float_as_int(m) >> 23) & 255) - 127;
          esh = esh < -126 ? -126 : (esh > 126 ? 126 : esh);
          u *= __int_as_float((127 - esh) << 23);
          A += esh;
        }
      }

      exch[wid][lane] = u;
      if (lane == 0) Ash[wid] = A;
    }

    // numerator: all 128 threads, steps [tid*4, tid*4+4)
    const int is64 = tgt_is64((const int*)traw);
    const long long tbase = (long long)b * (TT+1);
    float np = 0.f;
    int tga = ld_tgt(traw, is64, tbase + tid*4);
    #pragma unroll
    for (int k = 0; k < 4; ++k){
      int tgb = ld_tgt(traw, is64, tbase + tid*4 + k + 1);
      int ix = tga*VV + tgb;
      np += sb[(size_t)(tid*4 + k)*1024 + ix] + w_tx[ix] + w_dur[ix];
      tga = tgb;
    }
    numsm[tid] = np;
    __syncthreads();

    if (wid == 0){
      float alpha = exch[0][lane];
      float beta  = exch[1][lane];
      float ns = numsm[lane] + numsm[32+lane] + numsm[64+lane] + numsm[96+lane];

      // wait for chunk CTA b's product matrix (producers finish earlier; near-zero spin)
      if (lane == 0){ while (ld_acquire_(&g_flag[b]) == 0) {} }
      __syncwarp();

      const float* P = &g_P[(size_t)b * 1024];
      float n0=0.f, n1=0.f, n2=0.f, n3=0.f;
      #pragma unroll
      for (int i = 0; i < 32; i += 4){
        float p0 = P[(i  )*VV + lane];
        float p1 = P[(i+1)*VV + lane];
        float p2 = P[(i+2)*VV + lane];
        float p3 = P[(i+3)*VV + lane];
        n0 = fmaf(__shfl_sync(0xffffffffu, alpha, i  ), p0, n0);
        n1 = fmaf(__shfl_sync(0xffffffffu, alpha, i+1), p1, n1);
        n2 = fmaf(__shfl_sync(0xffffffffu, alpha, i+2), p2, n2);
        n3 = fmaf(__shfl_sync(0xffffffffu, alpha, i+3), p3, n3);
      }
      float term = ((n0 + n1) + (n2 + n3)) * beta;
      #pragma unroll
      for (int o = 16; o; o >>= 1){
        term += __shfl_xor_sync(0xffffffffu, term, o);
        ns   += __shfl_xor_sync(0xffffffffu, ns,   o);
      }

      if (lane == 0){
        int t0 = ld_tgt(traw, is64, tbase);
        int tT = ld_tgt(traw, is64, tbase + TT);
        float num = ns + w_init[t0] + w_final[tT];
        out[b] = num - F_LN2 * (lg2f_(term) + (float)(Ash[0] + Ash[1]) + g_Ac[b]);
        g_flag[b] = 0;   // reset for next graph replay (plain store; kernel boundary orders it)
      }
    }

  } else {
    // ================= CHUNK CTA: P = prod E_t, t in [LSC, LSC+MID) =================
    const int b = bid - 64;
    float* tile = (float*)(pool);             // NSTG*4KB
    float* E_sm = (float*)(pool + 16384);     // 2*4KB
    float* P_sm = (float*)(pool + 24576);     // 2*4KB
    const float* sb = scores + ((size_t)b*TT + LSC) * 1024;
    const int j  = lane;
    const int r0 = wid * 8;

    #pragma unroll
    for (int p = 0; p < NSTG-1; ++p){
      const uint32_t d = (uint32_t)__cvta_generic_to_shared(&tile[p*1024 + tid*8]);
      cpa16(d,      sb + p*1024 + tid*8);
      cpa16(d + 16, sb + p*1024 + tid*8 + 4);
      CPCOMMIT();
    }

    float c2own[8];
    #pragma unroll
    for (int k = 0; k < 8; ++k)
      c2own[k] = (w_tx[tid*8+k] + w_dur[tid*8+k]) * F_LOG2E;

    __syncthreads();
    int A = 0;

    for (int t = 0; t < MID; ++t){
      CPWAIT2();
      const int slot = t & (NSTG-1);
      {
        const float* tp = &tile[slot*1024 + tid*8];
        float e0 = ex2f_(fmaf(tp[0], F_LOG2E, c2own[0]));
        float e1 = ex2f_(fmaf(tp[1], F_LOG2E, c2own[1]));
        float e2 = ex2f_(fmaf(tp[2], F_LOG2E, c2own[2]));
        float e3 = ex2f_(fmaf(tp[3], F_LOG2E, c2own[3]));
        float e4 = ex2f_(fmaf(tp[4], F_LOG2E, c2own[4]));
        float e5 = ex2f_(fmaf(tp[5], F_LOG2E, c2own[5]));
        float e6 = ex2f_(fmaf(tp[6], F_LOG2E, c2own[6]));
        float e7 = ex2f_(fmaf(tp[7], F_LOG2E, c2own[7]));
        float* dst = (t == 0) ? &P_sm[0*1024 + tid*8] : &E_sm[(t&1)*1024 + tid*8];
        *(float4*)dst       = make_float4(e0, e1, e2, e3);
        *(float4*)(dst + 4) = make_float4(e4, e5, e6, e7);
      }
      __syncthreads();

      { int tl = t + NSTG - 1;
        if (tl < MID){
          const uint32_t d = (uint32_t)__cvta_generic_to_shared(&tile[(tl & (NSTG-1))*1024 + tid*8]);
          cpa16(d,      sb + (size_t)tl*1024 + tid*8);
          cpa16(d + 16, sb + (size_t)tl*1024 + tid*8 + 4);
        }
        CPCOMMIT();
      }

      if (t > 0){
        const int pbR = (t-1) & 1, pbW = t & 1, eb = t & 1;
        float p00 = P_sm[pbR*1024];
        int esh = ((__float_as_int(p00) >> 23) & 255) - 127;
        float sc = __int_as_float((127 - esh) << 23);
        A += esh;

        ull E2[16];
        #pragma unroll
        for (int i2 = 0; i2 < 16; ++i2)
          E2[i2] = pack2_(E_sm[eb*1024 + (2*i2)*VV + j], E_sm[eb*1024 + (2*i2+1)*VV + j]);

        ull acc[8];
        #pragma unroll
        for (int r = 0; r < 8; ++r) acc[r] = 0ull;
        #pragma unroll
        for (int i4 = 0; i4 < 8; ++i4){
          #pragma unroll
          for (int r = 0; r < 8; ++r){
            ulonglong2 qq = *(const ulonglong2*)&P_sm[pbR*1024 + (r0+r)*VV + 4*i4];
            acc[r] = fma2_(qq.x, E2[2*i4],   acc[r]);
            acc[r] = fma2_(qq.y, E2[2*i4+1], acc[r]);
          }
        }
        #pragma unroll
        for (int r = 0; r < 8; ++r){
          float lo, hi; unpack2_(acc[r], lo, hi);
          P_sm[pbW*1024 + (r0+r)*VV + j] = (lo + hi) * sc;
        }
      }
    }
    __syncthreads();
    const float* Pf = &P_sm[((MID-1) & 1)*1024];
    float* gout = &g_P[(size_t)b * 1024];
    for (int k = tid; k < 1024; k += 128) gout[k] = Pf[k];
    if (tid == 0) g_Ac[b] = (float)A;
    __threadfence();
    __syncthreads();
    if (tid == 0) st_release_(&g_flag[b], 1);
  }
}

extern "C" void kernel_launch(void* const* d_in, const int* in_sizes, int n_in,
                              void* d_out, int out_size)
{
  const float* scores  = (const float*)d_in[0];
  const void*  targets = d_in[1];
  const float* w_tx    = (const float*)d_in[2];
  const float* w_init  = (const float*)d_in[3];
  const float* w_final = (const float*)d_in[4];
  const float* w_dur   = (const float*)d_in[5];
  float* out = (float*)d_out;

  crf_main<<<128, 128>>>(scores, targets, w_tx, w_init, w_final, w_dur, out);
}